// round 14
// baseline (speedup 1.0000x reference)
#include <cuda_runtime.h>
#include <cuda_fp16.h>
#include <cstdint>

#define CZ   128
#define HD   64
#define P    128    // pixels per CTA
#define NT   1024
#define NW   32
#define XSTH 136    // halves per row: 272B stride -> ldmatrix 8-row fetches conflict-free
#define GST  72     // halves per row of G-gate tile

static __device__ __forceinline__ uint32_t smem_u32(const void* p) {
    return (uint32_t)__cvta_generic_to_shared(p);
}

static __device__ __forceinline__ void mma16(float* d,
    uint32_t a0, uint32_t a1, uint32_t a2, uint32_t a3, uint32_t b0, uint32_t b1)
{
    asm volatile("mma.sync.aligned.m16n8k16.row.col.f32.f16.f16.f32 "
        "{%0,%1,%2,%3}, {%4,%5,%6,%7}, {%8,%9}, {%0,%1,%2,%3};"
        : "+f"(d[0]), "+f"(d[1]), "+f"(d[2]), "+f"(d[3])
        : "r"(a0), "r"(a1), "r"(a2), "r"(a3), "r"(b0), "r"(b1));
}

static __device__ __forceinline__ void ldm4(
    uint32_t& r0, uint32_t& r1, uint32_t& r2, uint32_t& r3, uint32_t addr)
{
    asm volatile("ldmatrix.sync.aligned.m8n8.x4.shared.b16 {%0,%1,%2,%3}, [%4];"
        : "=r"(r0), "=r"(r1), "=r"(r2), "=r"(r3) : "r"(addr));
}

// Single-tile GEMM: 16 rows x 32 cols, K = 16*KT halves (QG / O phases).
static __device__ __forceinline__ void gemm16l(
    float acc[4][4], uint32_t aAddr, uint32_t bAddr, int KT)
{
    #pragma unroll
    for (int ks = 0; ks < KT; ks++) {
        const uint32_t kb = (uint32_t)ks * 32;
        uint32_t a0, a1, a2, a3, p0, p1, p2, p3, q0, q1, q2, q3;
        ldm4(a0, a1, a2, a3, aAddr + kb);
        ldm4(p0, p1, p2, p3, bAddr + kb);
        ldm4(q0, q1, q2, q3, bAddr + 16 * XSTH * 2 + kb);
        mma16(acc[0], a0, a1, a2, a3, p0, p1);
        mma16(acc[1], a0, a1, a2, a3, p2, p3);
        mma16(acc[2], a0, a1, a2, a3, q0, q1);
        mma16(acc[3], a0, a1, a2, a3, q2, q3);
    }
}

// Template-paired GEMM: B fragments loaded ONCE, applied to A0 (xs0) and A1 (xs1).
static __device__ __forceinline__ void gemm16lp(
    float acc0[4][4], float acc1[4][4],
    uint32_t a0Addr, uint32_t a1Addr, uint32_t bAddr)
{
    #pragma unroll
    for (int ks = 0; ks < 8; ks++) {
        const uint32_t kb = (uint32_t)ks * 32;
        uint32_t x0, x1, x2, x3, y0, y1, y2, y3, b0, b1, b2, b3;
        ldm4(x0, x1, x2, x3, a0Addr + kb);
        ldm4(y0, y1, y2, y3, a1Addr + kb);
        ldm4(b0, b1, b2, b3, bAddr + kb);
        mma16(acc0[0], x0, x1, x2, x3, b0, b1);
        mma16(acc0[1], x0, x1, x2, x3, b2, b3);
        mma16(acc1[0], y0, y1, y2, y3, b0, b1);
        mma16(acc1[1], y0, y1, y2, y3, b2, b3);
        ldm4(b0, b1, b2, b3, bAddr + 16 * XSTH * 2 + kb);
        mma16(acc0[2], x0, x1, x2, x3, b0, b1);
        mma16(acc0[3], x0, x1, x2, x3, b2, b3);
        mma16(acc1[2], y0, y1, y2, y3, b0, b1);
        mma16(acc1[3], y0, y1, y2, y3, b2, b3);
    }
}

// LayerNorm rows r0, r0+step, ... -> fp16 [row][k] stride XSTH.
static __device__ __forceinline__ void ln128s(
    const float* __restrict__ src, long base, int R, __half* dst,
    const float* __restrict__ g, const float* __restrict__ b,
    int r0, int step, int lane)
{
    const int c4 = lane * 4;
    const float4 g4 = *(const float4*)(g + c4);
    const float4 b4 = *(const float4*)(b + c4);
    #pragma unroll
    for (int r = r0; r < P; r += step) {
        long row = base + r;
        float4 x = make_float4(0.f, 0.f, 0.f, 0.f);
        if (row < R) x = *(const float4*)(src + row * (long)CZ + c4);
        float s = x.x + x.y + x.z + x.w;
        float q = fmaf(x.x, x.x, fmaf(x.y, x.y, fmaf(x.z, x.z, x.w * x.w)));
        #pragma unroll
        for (int o = 16; o; o >>= 1) {
            s += __shfl_xor_sync(0xffffffffu, s, o);
            q += __shfl_xor_sync(0xffffffffu, q, o);
        }
        float m  = s * (1.f / CZ);
        float v  = fmaxf(q * (1.f / CZ) - m * m, 0.f);
        float ri = rsqrtf(v + 1e-5f);
        __half* xr = dst + r * XSTH + c4;
        *(__half2*)(xr)     = __floats2half2_rn((x.x - m) * ri * g4.x + b4.x,
                                                (x.y - m) * ri * g4.y + b4.y);
        *(__half2*)(xr + 2) = __floats2half2_rn((x.z - m) * ri * g4.z + b4.z,
                                                (x.w - m) * ri * g4.w + b4.w);
    }
}

// Stage two k-major [128][64] weights into wt[n][k] fp16 (n<64: W1, else W2).
static __device__ __forceinline__ void stageW2(
    __half* wt, const float* __restrict__ W1, const float* __restrict__ W2, int tid)
{
    #pragma unroll 1
    for (int i = tid; i < 4096; i += NT) {
        const int m  = i >> 11;
        const int k  = (i >> 4) & 127;
        const int ng = i & 15;
        const float* Ws = m ? W2 : W1;
        float4 w = *(const float4*)(Ws + k * HD + ng * 4);
        const int n = m * 64 + ng * 4;
        wt[(n + 0) * XSTH + k] = __float2half_rn(w.x);
        wt[(n + 1) * XSTH + k] = __float2half_rn(w.y);
        wt[(n + 2) * XSTH + k] = __float2half_rn(w.z);
        wt[(n + 3) * XSTH + k] = __float2half_rn(w.w);
    }
}

__global__ void __launch_bounds__(NT, 1)
tpa_mma12(const float* __restrict__ tmpl, const float* __restrict__ pair,
          const float* __restrict__ lpg, const float* __restrict__ lpb,
          const float* __restrict__ ltg, const float* __restrict__ ltb,
          const float* __restrict__ Wq,  const float* __restrict__ Wk,
          const float* __restrict__ Wv,  const float* __restrict__ Wg,
          const float* __restrict__ bg,  const float* __restrict__ Wo,
          const float* __restrict__ bo,  float* __restrict__ out,
          int R, int T)
{
    extern __shared__ __align__(16) char smc[];
    __half* xs0 = (__half*)smc;               // 128 x XSTH : even-template LN buffer
    __half* xs1 = xs0 + P * XSTH;             // 128 x XSTH : odd-template LN buffer
    __half* wt  = xs1 + P * XSTH;             // 128 x XSTH : weights [n][k]
    __half* gs  = wt + P * XSTH;              // 128 x GST  : G gate (fp16)
    float4* qp4 = (float4*)(gs + P * GST);    // 16 x 4 x 32 float4 : K-warp private Q
    float*  rsA = (float*)(qp4 + 16 * 4 * 32);// 512 : rescale t_even (p*4+h)
    float*  wsA = rsA + 512;                  // 512
    float*  rsB = wsA + 512;                  // 512 : t_odd
    float*  wsB = rsB + 512;                  // 512
    float*  ls  = wsB + 512;                  // 512 : 1/l
    float*  bgs = ls + 512;                   // 64
    float*  bos = bgs + HD;                   // 128

    const int tid  = threadIdx.x;
    const int lane = tid & 31;
    const int wid  = tid >> 5;
    const int mt   = wid & 7;         // m-tile (16 rows)
    const int nq   = wid >> 3;        // n quarter (32 cols)
    const int gid  = lane >> 2;
    const int tig  = lane & 3;
    const bool isK = (nq < 2);
    const long base = (long)blockIdx.x * P;

    // ldmatrix lane-address offsets (bytes), fixed per thread
    const int lg  = lane >> 3, l7 = lane & 7;
    const uint32_t aOff = (uint32_t)((mt * 16 + (lg & 1) * 8 + l7) * XSTH
                                     + (lg >> 1) * 8) * 2;
    const uint32_t bOff = (uint32_t)((nq * 32 + (lg >> 1) * 8 + l7) * XSTH
                                     + (lg & 1) * 8) * 2;
    const uint32_t xs0A = smem_u32(xs0) + aOff;
    const uint32_t xs1A = smem_u32(xs1) + aOff;
    const uint32_t wtB  = smem_u32(wt) + bOff;

    if (tid < HD)  bgs[tid] = bg[tid];
    else if (tid >= 64 && tid < 64 + CZ) bos[tid - 64] = bo[tid - 64];

    // ---------------- Phase A: LN(pair)->xs0, Wq|Wg, QG GEMM ----------------
    ln128s(pair, base, R, xs0, lpg, lpb, wid, NW, lane);
    stageW2(wt, Wq, Wg, tid);
    __syncthreads();

    {
        float qf[4][4] = {};
        gemm16l(qf, xs0A, wtB, 8);
        if (isK) {                    // park Q fragments in private smem slot
            #pragma unroll
            for (int nt = 0; nt < 4; nt++)
                qp4[(wid * 4 + nt) * 32 + lane] =
                    make_float4(qf[nt][0], qf[nt][1], qf[nt][2], qf[nt][3]);
        } else {                      // sigmoid -> gs (fp16)
            const int r0 = mt * 16 + gid, r1 = r0 + 8;
            #pragma unroll
            for (int nt = 0; nt < 4; nt++) {
                const int c = (nq - 2) * 32 + nt * 8 + tig * 2;
                float g0 = 1.f / (1.f + __expf(-(qf[nt][0] + bgs[c])));
                float g1 = 1.f / (1.f + __expf(-(qf[nt][1] + bgs[c + 1])));
                float g2 = 1.f / (1.f + __expf(-(qf[nt][2] + bgs[c])));
                float g3 = 1.f / (1.f + __expf(-(qf[nt][3] + bgs[c + 1])));
                *(__half2*)(gs + r0 * GST + c) = __floats2half2_rn(g0, g1);
                *(__half2*)(gs + r1 * GST + c) = __floats2half2_rn(g2, g3);
            }
        }
    }
    __syncthreads();                  // xs0/wt reads done

    // stage Wk|Wv; LN t0 -> xs0 (warps 0-15), LN t1 -> xs1 (warps 16-31)
    stageW2(wt, Wk, Wv, tid);
    if (wid < 16) ln128s(tmpl, base, R, xs0, ltg, ltb, wid, 16, lane);
    else if (T > 1) ln128s(tmpl + (long)R * CZ, base, R, xs1, ltg, ltb, wid - 16, 16, lane);

    // pv: K-warps -> m4 = pv[0..3], l4 = pv[4..7]; V-warps -> vAcc = pv[0..15]
    float pv[16];
    #pragma unroll
    for (int i = 0; i < 16; i++) pv[i] = 0.f;
    if (isK) {
        #pragma unroll
        for (int i = 0; i < 4; i++) pv[i] = __int_as_float(0xff800000);
    }
    __syncthreads();

    // ---------------- pair loop: 2 templates per trip, 2 bars per trip ----------------
    const int NP = (T + 1) >> 1;
    #pragma unroll 1
    for (int pr = 0; pr < NP; pr++) {
        const bool doT1 = (2 * pr + 1) < T;
        const bool last = (pr == NP - 1);
        float kv0[4][4] = {}, kv1[4][4] = {};
        gemm16lp(kv0, kv1, xs0A, xs1A, wtB);

        if (isK) {                    // scores + online softmax for both templates
            float qf[4][4];
            #pragma unroll
            for (int nt = 0; nt < 4; nt++) {
                float4 v = qp4[(wid * 4 + nt) * 32 + lane];
                qf[nt][0] = v.x; qf[nt][1] = v.y; qf[nt][2] = v.z; qf[nt][3] = v.w;
            }
            #pragma unroll
            for (int tt = 0; tt < 2; tt++) {
                if (tt && !doT1) break;
                float (*kv)[4] = tt ? kv1 : kv0;
                float* rsb = tt ? rsB : rsA;
                float* wsb = tt ? wsB : wsA;
                float sc[2][2];
                #pragma unroll
                for (int hh = 0; hh < 2; hh++) {
                    const int nt0 = hh * 2;
                    #pragma unroll
                    for (int rh = 0; rh < 2; rh++) {
                        const int j = rh * 2;
                        float s = qf[nt0][j] * kv[nt0][j];
                        s = fmaf(qf[nt0][j + 1],     kv[nt0][j + 1],     s);
                        s = fmaf(qf[nt0 + 1][j],     kv[nt0 + 1][j],     s);
                        s = fmaf(qf[nt0 + 1][j + 1], kv[nt0 + 1][j + 1], s);
                        sc[rh][hh] = s;
                    }
                }
                #pragma unroll
                for (int rh = 0; rh < 2; rh++)
                    #pragma unroll
                    for (int hh = 0; hh < 2; hh++) {
                        float v = sc[rh][hh];
                        v += __shfl_xor_sync(0xffffffffu, v, 1);
                        v += __shfl_xor_sync(0xffffffffu, v, 2);
                        sc[rh][hh] = v;
                    }
                if (tig == 0) {
                    #pragma unroll
                    for (int rh = 0; rh < 2; rh++)
                        #pragma unroll
                        for (int hh = 0; hh < 2; hh++) {
                            const int i = rh * 2 + hh;
                            float sd = sc[rh][hh] * 0.25f;   // 1/sqrt(D=16)
                            float mn = fmaxf(pv[i], sd);
                            float rr = __expf(pv[i] - mn);
                            float ww = __expf(sd - mn);
                            pv[4 + i] = pv[4 + i] * rr + ww;
                            pv[i] = mn;
                            const int r = mt * 16 + rh * 8 + gid;
                            const int h = nq * 2 + hh;
                            rsb[r * 4 + h] = rr;
                            wsb[r * 4 + h] = ww;
                            if (last && (tt || !doT1))
                                ls[r * 4 + h] = 1.f / pv[4 + i];
                        }
                }
            }
        }
        __syncthreads();              // bar1: rs/ws (+ last: ls) ready; xs read done

        if (!isK) {                   // V online accumulate for both templates
            const int r0 = mt * 16 + gid, r1 = r0 + 8;
            #pragma unroll
            for (int nt = 0; nt < 4; nt++) {
                const int h = (nq - 2) * 2 + (nt >> 1);
                float a0 = fmaf(pv[nt * 4 + 0], rsA[r0 * 4 + h], wsA[r0 * 4 + h] * kv0[nt][0]);
                float a1 = fmaf(pv[nt * 4 + 1], rsA[r0 * 4 + h], wsA[r0 * 4 + h] * kv0[nt][1]);
                float a2 = fmaf(pv[nt * 4 + 2], rsA[r1 * 4 + h], wsA[r1 * 4 + h] * kv0[nt][2]);
                float a3 = fmaf(pv[nt * 4 + 3], rsA[r1 * 4 + h], wsA[r1 * 4 + h] * kv0[nt][3]);
                if (doT1) {
                    a0 = fmaf(a0, rsB[r0 * 4 + h], wsB[r0 * 4 + h] * kv1[nt][0]);
                    a1 = fmaf(a1, rsB[r0 * 4 + h], wsB[r0 * 4 + h] * kv1[nt][1]);
                    a2 = fmaf(a2, rsB[r1 * 4 + h], wsB[r1 * 4 + h] * kv1[nt][2]);
                    a3 = fmaf(a3, rsB[r1 * 4 + h], wsB[r1 * 4 + h] * kv1[nt][3]);
                }
                pv[nt * 4 + 0] = a0; pv[nt * 4 + 1] = a1;
                pv[nt * 4 + 2] = a2; pv[nt * 4 + 3] = a3;
            }
        }
        // LN prefetch for next pair (split warps across the two buffers)
        if (2 * pr + 2 < T && wid < 16)
            ln128s(tmpl + (long)(2 * pr + 2) * R * CZ, base, R, xs0, ltg, ltb, wid, 16, lane);
        if (2 * pr + 3 < T && wid >= 16)
            ln128s(tmpl + (long)(2 * pr + 3) * R * CZ, base, R, xs1, ltg, ltb, wid - 16, 16, lane);
        if (last) {                   // stage Wo[k=64][n=128] -> wt[n][k]
            #pragma unroll 1
            for (int i = tid; i < 2048; i += NT) {
                const int k = i >> 5, ng = i & 31;
                float4 w = *(const float4*)(Wo + k * CZ + ng * 4);
                const int n = ng * 4;
                wt[(n + 0) * XSTH + k] = __float2half_rn(w.x);
                wt[(n + 1) * XSTH + k] = __float2half_rn(w.y);
                wt[(n + 2) * XSTH + k] = __float2half_rn(w.z);
                wt[(n + 3) * XSTH + k] = __float2half_rn(w.w);
            }
        }
        __syncthreads();              // bar2: next xs / Wo / (V-acc done) ready
    }

    // ---------------- Phase C: vals -> xs0, O GEMM ----------------
    if (!isK) {                       // vals = vAcc * G * linv
        const int r0 = mt * 16 + gid, r1 = r0 + 8;
        #pragma unroll
        for (int nt = 0; nt < 4; nt++) {
            const int c = (nq - 2) * 32 + nt * 8 + tig * 2;
            const int h = (nq - 2) * 2 + (nt >> 1);
            float li0 = ls[r0 * 4 + h], li1 = ls[r1 * 4 + h];
            float2 g0 = __half22float2(*(__half2*)(gs + r0 * GST + c));
            float2 g1 = __half22float2(*(__half2*)(gs + r1 * GST + c));
            *(__half2*)(xs0 + r0 * XSTH + c) =
                __floats2half2_rn(pv[nt * 4 + 0] * g0.x * li0,
                                  pv[nt * 4 + 1] * g0.y * li0);
            *(__half2*)(xs0 + r1 * XSTH + c) =
                __floats2half2_rn(pv[nt * 4 + 2] * g1.x * li1,
                                  pv[nt * 4 + 3] * g1.y * li1);
        }
    }
    __syncthreads();                  // vals + Wo ready

    {
        float oc[4][4] = {};
        gemm16l(oc, xs0A, wtB, 4);
        const long r0 = base + mt * 16 + gid, r1 = r0 + 8;
        #pragma unroll
        for (int nt = 0; nt < 4; nt++) {
            const int c = nq * 32 + nt * 8 + tig * 2;
            if (r0 < R) {
                float2 v = make_float2(oc[nt][0] + bos[c], oc[nt][1] + bos[c + 1]);
                *(float2*)(out + r0 * (long)CZ + c) = v;
            }
            if (r1 < R) {
                float2 v = make_float2(oc[nt][2] + bos[c], oc[nt][3] + bos[c + 1]);
                *(float2*)(out + r1 * (long)CZ + c) = v;
            }
        }
    }
}

extern "C" void kernel_launch(void* const* d_in, const int* in_sizes, int n_in,
                              void* d_out, int out_size)
{
    const float* tmpl = (const float*)d_in[0];
    const float* pair = (const float*)d_in[1];
    const float* lpg  = (const float*)d_in[2];
    const float* lpb  = (const float*)d_in[3];
    const float* ltg  = (const float*)d_in[4];
    const float* ltb  = (const float*)d_in[5];
    const float* Wq   = (const float*)d_in[6];
    const float* Wk   = (const float*)d_in[7];
    const float* Wv   = (const float*)d_in[8];
    const float* Wg   = (const float*)d_in[9];
    const float* bg   = (const float*)d_in[10];
    const float* Wo   = (const float*)d_in[11];
    const float* bo   = (const float*)d_in[12];
    float* out = (float*)d_out;

    const int R = in_sizes[1] / CZ;           // b*n*n pixels
    const int T = in_sizes[0] / in_sizes[1];  // templates

    const size_t smem = (size_t)(3 * P * XSTH + P * GST) * sizeof(__half)
                      + (size_t)(16 * 4 * 32) * sizeof(float4)
                      + (size_t)(5 * 512 + HD + CZ) * sizeof(float);
    cudaFuncSetAttribute(tpa_mma12, cudaFuncAttributeMaxDynamicSharedMemorySize, (int)smem);

    const int grid = (R + P - 1) / P;
    tpa_mma12<<<grid, NT, smem>>>(tmpl, pair, lpg, lpb, ltg, ltb,
                                  Wq, Wk, Wv, Wg, bg, Wo, bo, out, R, T);
}

// round 16
// speedup vs baseline: 1.1833x; 1.1833x over previous
#include <cuda_runtime.h>
#include <cuda_fp16.h>
#include <cstdint>

#define CZ   128
#define HD   64
#define P    128    // pixels per CTA
#define NT   1024
#define NW   32
#define XSTH 136    // halves per row: 272B stride -> ldmatrix 8-row fetches conflict-free
#define GST  72     // halves per row of G-gate tile
#define WTILE (P * XSTH)   // 17408 halves per weight tile

// Pre-converted fp16 weight tiles in [n][XSTH] layout (zero-init padding).
__device__ __align__(16) __half g_wqg[WTILE];
__device__ __align__(16) __half g_wkv[WTILE];
__device__ __align__(16) __half g_wo [WTILE];

__global__ void prep_weights(const float* __restrict__ Wq, const float* __restrict__ Wk,
                             const float* __restrict__ Wv, const float* __restrict__ Wg,
                             const float* __restrict__ Wo)
{
    const int i = blockIdx.x * blockDim.x + threadIdx.x;
    if (i < 16384) {                       // Wq|Wg -> g_wqg[n][k]
        const int n = i & 127, k = i >> 7;
        float w = (n < 64) ? Wq[k * HD + n] : Wg[k * HD + (n - 64)];
        g_wqg[n * XSTH + k] = __float2half_rn(w);
    } else if (i < 32768) {                // Wk|Wv -> g_wkv[n][k]
        const int j = i - 16384;
        const int n = j & 127, k = j >> 7;
        float w = (n < 64) ? Wk[k * HD + n] : Wv[k * HD + (n - 64)];
        g_wkv[n * XSTH + k] = __float2half_rn(w);
    } else if (i < 40960) {                // Wo -> g_wo[n][k], k<64
        const int j = i - 32768;
        const int n = j & 127, k = j >> 7;
        g_wo[n * XSTH + k] = __float2half_rn(Wo[k * CZ + n]);
    }
}

static __device__ __forceinline__ uint32_t smem_u32(const void* p) {
    return (uint32_t)__cvta_generic_to_shared(p);
}
static __device__ __forceinline__ uint32_t h2u(__half2 h) {
    return *(uint32_t*)&h;
}

static __device__ __forceinline__ void mma16(float* d,
    uint32_t a0, uint32_t a1, uint32_t a2, uint32_t a3, uint32_t b0, uint32_t b1)
{
    asm volatile("mma.sync.aligned.m16n8k16.row.col.f32.f16.f16.f32 "
        "{%0,%1,%2,%3}, {%4,%5,%6,%7}, {%8,%9}, {%0,%1,%2,%3};"
        : "+f"(d[0]), "+f"(d[1]), "+f"(d[2]), "+f"(d[3])
        : "r"(a0), "r"(a1), "r"(a2), "r"(a3), "r"(b0), "r"(b1));
}

static __device__ __forceinline__ void ldm4(
    uint32_t& r0, uint32_t& r1, uint32_t& r2, uint32_t& r3, uint32_t addr)
{
    asm volatile("ldmatrix.sync.aligned.m8n8.x4.shared.b16 {%0,%1,%2,%3}, [%4];"
        : "=r"(r0), "=r"(r1), "=r"(r2), "=r"(r3) : "r"(addr));
}

// Warp computes 16 rows x 32 cols; K = 16*KT halves.
// Per k-step: 1 A-ldmatrix.x4 + 2 B-ldmatrix.x4 feed 4 MMAs.
static __device__ __forceinline__ void gemm16l(
    float acc[4][4], uint32_t aAddr, uint32_t bAddr, int KT)
{
    #pragma unroll
    for (int ks = 0; ks < KT; ks++) {
        const uint32_t kb = (uint32_t)ks * 32;
        uint32_t a0, a1, a2, a3, p0, p1, p2, p3, q0, q1, q2, q3;
        ldm4(a0, a1, a2, a3, aAddr + kb);
        ldm4(p0, p1, p2, p3, bAddr + kb);
        ldm4(q0, q1, q2, q3, bAddr + 16 * XSTH * 2 + kb);
        mma16(acc[0], a0, a1, a2, a3, p0, p1);
        mma16(acc[1], a0, a1, a2, a3, p2, p3);
        mma16(acc[2], a0, a1, a2, a3, q0, q1);
        mma16(acc[3], a0, a1, a2, a3, q2, q3);
    }
}

// LayerNorm: warp handles 2 rows per trip via 16-lane groups (4 shfl levels),
// packed STS.128 output. Covers rows {2w+half + i*2W}.
static __device__ __forceinline__ void ln128s(
    const float* __restrict__ src, long base, int R, __half* dst,
    const float* __restrict__ g, const float* __restrict__ b,
    int w, int W, int lane)
{
    const int half = lane >> 4;
    const int sl   = lane & 15;
    const int c8   = sl * 8;
    const float4 ga = *(const float4*)(g + c8);
    const float4 gb = *(const float4*)(g + c8 + 4);
    const float4 ba = *(const float4*)(b + c8);
    const float4 bb = *(const float4*)(b + c8 + 4);
    #pragma unroll
    for (int rb = 2 * w; rb < P; rb += 2 * W) {
        const int r = rb + half;
        long row = base + r;
        float4 xa = make_float4(0.f, 0.f, 0.f, 0.f);
        float4 xb = make_float4(0.f, 0.f, 0.f, 0.f);
        if (row < R) {
            xa = *(const float4*)(src + row * (long)CZ + c8);
            xb = *(const float4*)(src + row * (long)CZ + c8 + 4);
        }
        float s = (xa.x + xa.y) + (xa.z + xa.w) + (xb.x + xb.y) + (xb.z + xb.w);
        float q = fmaf(xa.x, xa.x, fmaf(xa.y, xa.y, fmaf(xa.z, xa.z, xa.w * xa.w)));
        q = fmaf(xb.x, xb.x, fmaf(xb.y, xb.y, fmaf(xb.z, xb.z, fmaf(xb.w, xb.w, q))));
        #pragma unroll
        for (int o = 8; o; o >>= 1) {           // 16-lane group reduction
            s += __shfl_xor_sync(0xffffffffu, s, o);
            q += __shfl_xor_sync(0xffffffffu, q, o);
        }
        float m  = s * (1.f / CZ);
        float v  = fmaxf(q * (1.f / CZ) - m * m, 0.f);
        float ri = rsqrtf(v + 1e-5f);
        __half2 h0 = __floats2half2_rn((xa.x - m) * ri * ga.x + ba.x,
                                       (xa.y - m) * ri * ga.y + ba.y);
        __half2 h1 = __floats2half2_rn((xa.z - m) * ri * ga.z + ba.z,
                                       (xa.w - m) * ri * ga.w + ba.w);
        __half2 h2 = __floats2half2_rn((xb.x - m) * ri * gb.x + bb.x,
                                       (xb.y - m) * ri * gb.y + bb.y);
        __half2 h3 = __floats2half2_rn((xb.z - m) * ri * gb.z + bb.z,
                                       (xb.w - m) * ri * gb.w + bb.w);
        uint4 u;
        u.x = h2u(h0); u.y = h2u(h1);
        u.z = h2u(h2); u.w = h2u(h3);
        *(uint4*)(dst + r * XSTH + c8) = u;
    }
}

// Stage a pre-converted weight tile: pure 16B copy.
static __device__ __forceinline__ void stageCopy(
    __half* wt, const __half* __restrict__ src, int tid)
{
    const uint4* s = (const uint4*)src;
    uint4* d = (uint4*)wt;
    #pragma unroll 1
    for (int i = tid; i < WTILE / 8; i += NT) d[i] = s[i];
}

__global__ void __launch_bounds__(NT, 1)
tpa_mma13(const float* __restrict__ tmpl, const float* __restrict__ pair,
          const float* __restrict__ lpg, const float* __restrict__ lpb,
          const float* __restrict__ ltg, const float* __restrict__ ltb,
          const float* __restrict__ bg,  const float* __restrict__ bo,
          float* __restrict__ out, int R, int T)
{
    extern __shared__ __align__(16) char smc[];
    __half* xs0 = (__half*)smc;               // 128 x XSTH : LN buffer A
    __half* xs1 = xs0 + P * XSTH;             // 128 x XSTH : LN buffer B
    __half* wt  = xs1 + P * XSTH;             // 128 x XSTH : weights [n][k]
    __half* gs  = wt + P * XSTH;              // 128 x GST  : G gate (fp16)
    float*  rs0 = (float*)(gs + P * GST);     // 512 : rescale parity 0 (p*4+h)
    float*  ws0 = rs0 + 512;                  // 512
    float*  rs1 = ws0 + 512;                  // 512 : parity 1
    float*  ws1 = rs1 + 512;                  // 512
    float*  ls  = ws1 + 512;                  // 512 : 1/l
    float*  bgs = ls + 512;                   // 64
    float*  bos = bgs + HD;                   // 128

    const int tid  = threadIdx.x;
    const int lane = tid & 31;
    const int wid  = tid >> 5;
    const int mt   = wid & 7;         // m-tile (16 rows)
    const int nq   = wid >> 3;        // n quarter (32 cols)
    const int gid  = lane >> 2;
    const int tig  = lane & 3;
    const bool isK = (nq < 2);
    const long base = (long)blockIdx.x * P;

    // ldmatrix lane-address offsets (bytes), fixed per thread
    const int lg  = lane >> 3, l7 = lane & 7;
    const uint32_t aOff = (uint32_t)((mt * 16 + (lg & 1) * 8 + l7) * XSTH
                                     + (lg >> 1) * 8) * 2;
    const uint32_t bOff = (uint32_t)((nq * 32 + (lg >> 1) * 8 + l7) * XSTH
                                     + (lg & 1) * 8) * 2;
    const uint32_t xs0A = smem_u32(xs0) + aOff;
    const uint32_t xs1A = smem_u32(xs1) + aOff;
    const uint32_t wtB  = smem_u32(wt) + bOff;

    if (tid < HD)  bgs[tid] = bg[tid];
    else if (tid >= 64 && tid < 64 + CZ) bos[tid - 64] = bo[tid - 64];

    // ---------------- Phase A: LN(pair)->xs0, Wq|Wg, QG GEMM ----------------
    ln128s(pair, base, R, xs0, lpg, lpb, wid, NW, lane);
    stageCopy(wt, g_wqg, tid);
    __syncthreads();

    float qf[4][4] = {};              // K-warps keep Q; V-warps: temp for G
    gemm16l(qf, xs0A, wtB, 8);
    if (!isK) {                       // sigmoid -> gs (fp16), qf dead afterwards
        const int r0 = mt * 16 + gid, r1 = r0 + 8;
        #pragma unroll
        for (int nt = 0; nt < 4; nt++) {
            const int c = (nq - 2) * 32 + nt * 8 + tig * 2;
            float g0 = 1.f / (1.f + __expf(-(qf[nt][0] + bgs[c])));
            float g1 = 1.f / (1.f + __expf(-(qf[nt][1] + bgs[c + 1])));
            float g2 = 1.f / (1.f + __expf(-(qf[nt][2] + bgs[c])));
            float g3 = 1.f / (1.f + __expf(-(qf[nt][3] + bgs[c + 1])));
            *(__half2*)(gs + r0 * GST + c) = __floats2half2_rn(g0, g1);
            *(__half2*)(gs + r1 * GST + c) = __floats2half2_rn(g2, g3);
        }
    }
    __syncthreads();                  // xs0/wt reads done

    // stage Wk|Wv; LN t0 -> xs0 (warps 0-15), LN t1 -> xs1 (warps 16-31)
    stageCopy(wt, g_wkv, tid);
    if (wid < 16) ln128s(tmpl, base, R, xs0, ltg, ltb, wid, 16, lane);
    else if (T > 1) ln128s(tmpl + (long)R * CZ, base, R, xs1, ltg, ltb, wid - 16, 16, lane);

    // pv: K-warps -> m4 = pv[0..3], l4 = pv[4..7]; V-warps -> vAcc = pv[0..15]
    float pv[16];
    #pragma unroll
    for (int i = 0; i < 16; i++) pv[i] = 0.f;
    if (isK) {
        #pragma unroll
        for (int i = 0; i < 4; i++) pv[i] = __int_as_float(0xff800000);
    }
    __syncthreads();

    // ---------------- template loop: ONE sync per template ----------------
    #pragma unroll 1
    for (int t = 0; t < T; t++) {
        float* rsb = (t & 1) ? rs1 : rs0;
        float* wsb = (t & 1) ? ws1 : ws0;
        float kv[4][4] = {};
        gemm16l(kv, (t & 1) ? xs1A : xs0A, wtB, 8);

        if (isK) {                    // in-fragment scores + online softmax
            float sc[2][2];           // [rowhalf][headhalf]
            #pragma unroll
            for (int hh = 0; hh < 2; hh++) {
                const int nt0 = hh * 2;
                #pragma unroll
                for (int rh = 0; rh < 2; rh++) {
                    const int j = rh * 2;
                    float s = qf[nt0][j] * kv[nt0][j];
                    s = fmaf(qf[nt0][j + 1],     kv[nt0][j + 1],     s);
                    s = fmaf(qf[nt0 + 1][j],     kv[nt0 + 1][j],     s);
                    s = fmaf(qf[nt0 + 1][j + 1], kv[nt0 + 1][j + 1], s);
                    sc[rh][hh] = s;
                }
            }
            #pragma unroll
            for (int rh = 0; rh < 2; rh++)
                #pragma unroll
                for (int hh = 0; hh < 2; hh++) {
                    float v = sc[rh][hh];
                    v += __shfl_xor_sync(0xffffffffu, v, 1);
                    v += __shfl_xor_sync(0xffffffffu, v, 2);
                    sc[rh][hh] = v;
                }
            if (tig == 0) {
                #pragma unroll
                for (int rh = 0; rh < 2; rh++)
                    #pragma unroll
                    for (int hh = 0; hh < 2; hh++) {
                        const int i = rh * 2 + hh;
                        float sd = sc[rh][hh] * 0.25f;    // 1/sqrt(D=16)
                        float mn = fmaxf(pv[i], sd);
                        float rr = __expf(pv[i] - mn);
                        float ww = __expf(sd - mn);
                        pv[4 + i] = pv[4 + i] * rr + ww;
                        pv[i] = mn;
                        const int r = mt * 16 + rh * 8 + gid;
                        const int h = nq * 2 + hh;
                        rsb[r * 4 + h] = rr;
                        wsb[r * 4 + h] = ww;
                        if (t == T - 1)
                            ls[r * 4 + h] = 1.f / pv[4 + i];
                    }
            }
        }
        __syncthreads();              // rs/ws[t&1] (+ last: ls) ready; xs[t&1] read done

        if (!isK) {                   // V online accumulate into pv
            const int r0 = mt * 16 + gid, r1 = r0 + 8;
            #pragma unroll
            for (int nt = 0; nt < 4; nt++) {
                const int h = (nq - 2) * 2 + (nt >> 1);
                float rr0 = rsb[r0 * 4 + h], ww0 = wsb[r0 * 4 + h];
                float rr1 = rsb[r1 * 4 + h], ww1 = wsb[r1 * 4 + h];
                pv[nt * 4 + 0] = fmaf(pv[nt * 4 + 0], rr0, ww0 * kv[nt][0]);
                pv[nt * 4 + 1] = fmaf(pv[nt * 4 + 1], rr0, ww0 * kv[nt][1]);
                pv[nt * 4 + 2] = fmaf(pv[nt * 4 + 2], rr1, ww1 * kv[nt][2]);
                pv[nt * 4 + 3] = fmaf(pv[nt * 4 + 3], rr1, ww1 * kv[nt][3]);
            }
        }
        if (t + 2 < T)                // prefetch LN(t+2) into just-freed buffer
            ln128s(tmpl + (long)(t + 2) * R * CZ, base, R,
                   (t & 1) ? xs1 : xs0, ltg, ltb, wid, NW, lane);
        if (t == T - 1)               // stage Wo tile (pure copy)
            stageCopy(wt, g_wo, tid);
    }

    // ---------------- Phase C: vals -> xs[T&1], O GEMM ----------------
    __half* xsv = (T & 1) ? xs1 : xs0;    // buffer NOT read by last GEMM
    const uint32_t xsvA = (T & 1) ? xs1A : xs0A;
    if (!isK) {                           // vals = vAcc * G * linv
        const int r0 = mt * 16 + gid, r1 = r0 + 8;
        #pragma unroll
        for (int nt = 0; nt < 4; nt++) {
            const int c = (nq - 2) * 32 + nt * 8 + tig * 2;
            const int h = (nq - 2) * 2 + (nt >> 1);
            float li0 = ls[r0 * 4 + h], li1 = ls[r1 * 4 + h];
            float2 g0 = __half22float2(*(__half2*)(gs + r0 * GST + c));
            float2 g1 = __half22float2(*(__half2*)(gs + r1 * GST + c));
            *(__half2*)(xsv + r0 * XSTH + c) =
                __floats2half2_rn(pv[nt * 4 + 0] * g0.x * li0,
                                  pv[nt * 4 + 1] * g0.y * li0);
            *(__half2*)(xsv + r1 * XSTH + c) =
                __floats2half2_rn(pv[nt * 4 + 2] * g1.x * li1,
                                  pv[nt * 4 + 3] * g1.y * li1);
        }
    }
    __syncthreads();                  // vals + Wo ready

    {
        float oc[4][4] = {};
        gemm16l(oc, xsvA, wtB, 4);
        const long r0 = base + mt * 16 + gid, r1 = r0 + 8;
        #pragma unroll
        for (int nt = 0; nt < 4; nt++) {
            const int c = nq * 32 + nt * 8 + tig * 2;
            if (r0 < R) {
                float2 v = make_float2(oc[nt][0] + bos[c], oc[nt][1] + bos[c + 1]);
                *(float2*)(out + r0 * (long)CZ + c) = v;
            }
            if (r1 < R) {
                float2 v = make_float2(oc[nt][2] + bos[c], oc[nt][3] + bos[c + 1]);
                *(float2*)(out + r1 * (long)CZ + c) = v;
            }
        }
    }
}

extern "C" void kernel_launch(void* const* d_in, const int* in_sizes, int n_in,
                              void* d_out, int out_size)
{
    const float* tmpl = (const float*)d_in[0];
    const float* pair = (const float*)d_in[1];
    const float* lpg  = (const float*)d_in[2];
    const float* lpb  = (const float*)d_in[3];
    const float* ltg  = (const float*)d_in[4];
    const float* ltb  = (const float*)d_in[5];
    const float* Wq   = (const float*)d_in[6];
    const float* Wk   = (const float*)d_in[7];
    const float* Wv   = (const float*)d_in[8];
    const float* Wg   = (const float*)d_in[9];
    const float* bg   = (const float*)d_in[10];
    const float* Wo   = (const float*)d_in[11];
    const float* bo   = (const float*)d_in[12];
    float* out = (float*)d_out;

    const int R = in_sizes[1] / CZ;           // b*n*n pixels
    const int T = in_sizes[0] / in_sizes[1];  // templates

    prep_weights<<<40, 1024>>>(Wq, Wk, Wv, Wg, Wo);

    const size_t smem = (size_t)(3 * P * XSTH + P * GST) * sizeof(__half)
                      + (size_t)(5 * 512 + HD + CZ) * sizeof(float);
    cudaFuncSetAttribute(tpa_mma13, cudaFuncAttributeMaxDynamicSharedMemorySize, (int)smem);

    const int grid = (R + P - 1) / P;
    tpa_mma13<<<grid, NT, smem>>>(tmpl, pair, lpg, lpb, ltg, ltb,
                                  bg, bo, out, R, T);
}